// round 5
// baseline (speedup 1.0000x reference)
#include <cuda_runtime.h>
#include <cuda_fp16.h>
#include <cstdint>

#define B_    32
#define N_    577
#define H_    12
#define DH_   64
#define DIM_  768
#define INNER 768
#define M_TOT (B_ * N_)   // 18464
#define NEG_MASK (-987654321.0f)

// ---------------- scratch (device globals: no runtime allocation) -------------
__device__ __align__(128) __half g_qh[(size_t)B_ * H_ * N_ * DH_];
__device__ __align__(128) __half g_kh[(size_t)B_ * H_ * N_ * DH_];
__device__ __align__(128) __half g_vh[(size_t)B_ * H_ * N_ * DH_];
__device__ __align__(128) __half g_xh[(size_t)M_TOT * DIM_];
__device__ __align__(128) __half g_atth[(size_t)M_TOT * INNER];
__device__ __align__(128) __half g_wqkvt[(size_t)2304 * DIM_];
__device__ __align__(128) __half g_woutt[(size_t)DIM_ * INNER];

__device__ __forceinline__ uint32_t smem_to_u32(const void* p) {
    uint32_t a;
    asm("{ .reg .u64 t; cvta.to.shared.u64 t, %1; cvt.u32.u64 %0, t; }" : "=r"(a) : "l"(p));
    return a;
}

#define MMA_F16(acc, a0, a1, a2, a3, b0, b1) \
    asm volatile("mma.sync.aligned.m16n8k16.row.col.f32.f16.f16.f32 " \
        "{%0,%1,%2,%3}, {%4,%5,%6,%7}, {%8,%9}, {%0,%1,%2,%3};" \
        : "+f"((acc)[0]), "+f"((acc)[1]), "+f"((acc)[2]), "+f"((acc)[3]) \
        : "r"(a0), "r"(a1), "r"(a2), "r"(a3), "r"(b0), "r"(b1))

#define LDSM_X4(r0, r1, r2, r3, addr) \
    asm volatile("ldmatrix.sync.aligned.m8n8.x4.shared.b16 {%0,%1,%2,%3}, [%4];" \
        : "=r"(r0), "=r"(r1), "=r"(r2), "=r"(r3) : "r"(addr))

#define LDSM_X4_T(r0, r1, r2, r3, addr) \
    asm volatile("ldmatrix.sync.aligned.m8n8.x4.trans.shared.b16 {%0,%1,%2,%3}, [%4];" \
        : "=r"(r0), "=r"(r1), "=r"(r2), "=r"(r3) : "r"(addr))

__device__ __forceinline__ uint32_t pack_h2(float lo, float hi) {
    __half2 h = __floats2half2_rn(lo, hi);
    return *(uint32_t*)&h;
}

// ---------------- HMMA GEMM: 128x128 tile, BK=64, 3-stage cp.async -------------
// A [M,768] fp16 row-major; Bt [Ncols,768] fp16 (K-contiguous).
// mode 0: scatter fp16 into g_qh/g_kh/g_vh [b,h,n,d];  mode 1: +bias -> Cout fp32.
__global__ __launch_bounds__(256) void hgemm_mma(
    const __half* __restrict__ A, const __half* __restrict__ Bt,
    int Mrows, int mode, const float* __restrict__ bias, float* __restrict__ Cout)
{
    extern __shared__ char smem[];
    const uint32_t sbase = smem_to_u32(smem);   // 3 bufs x (A 16K + B 16K)

    const int tid = threadIdx.x;
    const int wid = tid >> 5, lid = tid & 31;
    const int n0 = blockIdx.x * 128, m0 = blockIdx.y * 128;
    const int wm = wid >> 1, wn = wid & 1;

    const int ldr = tid >> 3;
    const int ldc = tid & 7;

    float acc[2][8][4];
#pragma unroll
    for (int mi = 0; mi < 2; mi++)
#pragma unroll
        for (int ni = 0; ni < 8; ni++)
#pragma unroll
            for (int e = 0; e < 4; e++) acc[mi][ni][e] = 0.f;

    auto prefetch = [&](int c) {
        uint32_t sA = sbase + (c % 3) * 32768;
        uint32_t sB = sA + 16384;
#pragma unroll
        for (int i = 0; i < 4; i++) {
            int row = ldr + i * 32;
            uint32_t off = row * 128 + ldc * 16;
            uint32_t sw = off ^ ((off >> 3) & 0x70);
            const void* gA = A + (size_t)(m0 + row) * 768 + c * 64 + ldc * 8;
            int szA = (m0 + row < Mrows) ? 16 : 0;
            asm volatile("cp.async.cg.shared.global [%0], [%1], 16, %2;"
                         :: "r"(sA + sw), "l"(gA), "r"(szA));
            const void* gB = Bt + (size_t)(n0 + row) * 768 + c * 64 + ldc * 8;
            asm volatile("cp.async.cg.shared.global [%0], [%1], 16;"
                         :: "r"(sB + sw), "l"(gB));
        }
        asm volatile("cp.async.commit_group;");
    };

    prefetch(0);
    prefetch(1);

    for (int c = 0; c < 12; c++) {
        if (c < 11) asm volatile("cp.async.wait_group 1;");
        else        asm volatile("cp.async.wait_group 0;");
        __syncthreads();                 // chunk c visible; buf (c+2)%3 free
        if (c + 2 < 12) prefetch(c + 2); // overlap with compute below

        const uint32_t sA = sbase + (c % 3) * 32768 + (wm * 32) * 128;
        const uint32_t sB = sbase + (c % 3) * 32768 + 16384 + (wn * 64) * 128;

#pragma unroll
        for (int k16 = 0; k16 < 4; k16++) {
            uint32_t a[2][4];
#pragma unroll
            for (int mi = 0; mi < 2; mi++) {
                int row = mi * 16 + (lid & 15);
                uint32_t off = row * 128 + k16 * 32 + (lid >> 4) * 16;
                uint32_t sw = off ^ ((off >> 3) & 0x70);
                LDSM_X4(a[mi][0], a[mi][1], a[mi][2], a[mi][3], sA + sw);
            }
            uint32_t b[8][2];
#pragma unroll
            for (int nj = 0; nj < 4; nj++) {
                int row = nj * 16 + ((lid >> 4) & 1) * 8 + (lid & 7);
                uint32_t off = row * 128 + k16 * 32 + ((lid >> 3) & 1) * 16;
                uint32_t sw = off ^ ((off >> 3) & 0x70);
                uint32_t r0, r1, r2, r3;
                LDSM_X4(r0, r1, r2, r3, sB + sw);
                b[nj * 2][0] = r0;     b[nj * 2][1] = r1;
                b[nj * 2 + 1][0] = r2; b[nj * 2 + 1][1] = r3;
            }
#pragma unroll
            for (int mi = 0; mi < 2; mi++)
#pragma unroll
                for (int ni = 0; ni < 8; ni++)
                    MMA_F16(acc[mi][ni], a[mi][0], a[mi][1], a[mi][2], a[mi][3],
                            b[ni][0], b[ni][1]);
        }
    }

    const int gid = lid >> 2, qid = lid & 3;
#pragma unroll
    for (int mi = 0; mi < 2; mi++) {
#pragma unroll
        for (int half = 0; half < 2; half++) {
            int m = m0 + wm * 32 + mi * 16 + gid + half * 8;
            if (m >= Mrows) continue;
            if (mode == 0) {
                int bb = m / N_, nn = m - bb * N_;
#pragma unroll
                for (int ni = 0; ni < 8; ni++) {
                    int col = n0 + wn * 64 + ni * 8 + qid * 2;
                    int which = col / INNER;
                    int inr = col - which * INNER;
                    int hh = inr >> 6, dd = inr & 63;
                    __half* dst = ((which == 0) ? g_qh : (which == 1) ? g_kh : g_vh)
                                + ((((size_t)bb * H_ + hh) * N_ + nn) << 6) + dd;
                    *(__half2*)dst = __floats2half2_rn(acc[mi][ni][half * 2],
                                                       acc[mi][ni][half * 2 + 1]);
                }
            } else {
                float* crow = Cout + (size_t)m * 768;
#pragma unroll
                for (int ni = 0; ni < 8; ni++) {
                    int col = n0 + wn * 64 + ni * 8 + qid * 2;
                    float2 bv = *(const float2*)(bias + col);
                    *(float2*)(crow + col) = make_float2(acc[mi][ni][half * 2] + bv.x,
                                                         acc[mi][ni][half * 2 + 1] + bv.y);
                }
            }
        }
    }
}

// ---------------- prologue conversions -----------------------------------------
__global__ void f32_to_f16_vec(const float* __restrict__ in, __half* __restrict__ out, int n4)
{
    int i = blockIdx.x * blockDim.x + threadIdx.x;
    if (i < n4) {
        float4 v = ((const float4*)in)[i];
        ((__half2*)out)[2 * i + 0] = __floats2half2_rn(v.x, v.y);
        ((__half2*)out)[2 * i + 1] = __floats2half2_rn(v.z, v.w);
    }
}
__global__ void transpose_f16(const float* __restrict__ W, __half* __restrict__ Wt,
                              int rows, int cols)
{
    __shared__ float t[32][33];
    int x = blockIdx.x * 32 + threadIdx.x;
    int y = blockIdx.y * 32 + threadIdx.y;
    t[threadIdx.y][threadIdx.x] = W[(size_t)y * cols + x];
    __syncthreads();
    int xo = blockIdx.y * 32 + threadIdx.x;
    int yo = blockIdx.x * 32 + threadIdx.y;
    Wt[(size_t)yo * rows + xo] = __float2half(t[threadIdx.x][threadIdx.y]);
}

// ---------------- HMMA flash attention -----------------------------------------
// CTA: 128 q-rows x one (b,h); 8 warps x 16 rows. Key tiles of 64, 3-stage pipeline.
// smem: Q 16KB | {K,V} x 3 bufs (16KB each) = 65536 B
__global__ __launch_bounds__(256) void attn_mma(const float* __restrict__ scale)
{
    extern __shared__ char smem[];
    const uint32_t sb = smem_to_u32(smem);
    const uint32_t sQ = sb;

    const int tid = threadIdx.x, wid = tid >> 5, lid = tid & 31;
    const int qt = blockIdx.x, h = blockIdx.y, b = blockIdx.z;
    const int q0 = qt * 128;
    const float sc = scale[h];
    const size_t hbase = (size_t)(b * H_ + h) * N_ * 64;
    const __half* Qg = g_qh + hbase;
    const __half* Kg = g_kh + hbase;
    const __half* Vg = g_vh + hbase;

    // Q tile 128x64 -> smem (zfill OOB rows)
#pragma unroll
    for (int i = 0; i < 4; i++) {
        int idx = tid + i * 256;
        int row = idx >> 3, cc = idx & 7;
        uint32_t off = row * 128 + cc * 16;
        uint32_t sw = off ^ ((off >> 3) & 0x70);
        const void* src = Qg + (size_t)(q0 + row) * 64 + cc * 8;
        int sz = (q0 + row < N_) ? 16 : 0;
        asm volatile("cp.async.cg.shared.global [%0], [%1], 16, %2;"
                     :: "r"(sQ + sw), "l"(src), "r"(sz));
    }
    asm volatile("cp.async.commit_group;");

    auto ldKV = [&](int kt) {
        uint32_t sK = sb + 16384 + (kt % 3) * 16384;
        uint32_t sV = sK + 8192;
        int k0 = kt * 64;
#pragma unroll
        for (int i = 0; i < 2; i++) {
            int idx = tid + i * 256;
            int row = idx >> 3, cc = idx & 7;
            uint32_t off = row * 128 + cc * 16;
            uint32_t sw = off ^ ((off >> 3) & 0x70);
            int gj = k0 + row;
            int sz = (gj < N_) ? 16 : 0;
            const void* srcK = Kg + (size_t)gj * 64 + cc * 8;
            const void* srcV = Vg + (size_t)gj * 64 + cc * 8;
            asm volatile("cp.async.cg.shared.global [%0], [%1], 16, %2;"
                         :: "r"(sK + sw), "l"(srcK), "r"(sz));
            asm volatile("cp.async.cg.shared.global [%0], [%1], 16, %2;"
                         :: "r"(sV + sw), "l"(srcV), "r"(sz));
        }
        asm volatile("cp.async.commit_group;");
    };
    ldKV(0);
    ldKV(1);

    float m0r = -1e30f, m1r = -1e30f, l0r = 0.f, l1r = 0.f;
    float oacc[8][4];
#pragma unroll
    for (int nd = 0; nd < 8; nd++)
#pragma unroll
        for (int e = 0; e < 4; e++) oacc[nd][e] = 0.f;

    const int gi0 = q0 + wid * 16 + (lid >> 2);
    const int gi1 = gi0 + 8;
    const int cbx = (lid & 3) * 2;

    for (int kt = 0; kt < 10; kt++) {
        if (kt < 9) asm volatile("cp.async.wait_group 1;");
        else        asm volatile("cp.async.wait_group 0;");
        __syncthreads();                 // tile kt (and Q) visible; buf (kt+2)%3 free
        if (kt + 2 < 10) ldKV(kt + 2);

        const uint32_t sK = sb + 16384 + (kt % 3) * 16384;
        const uint32_t sV = sK + 8192;
        const int k0 = kt * 64;

        // ---- S = Q K^T (warp: 16 rows x 64 keys) ----
        float sacc[8][4];
#pragma unroll
        for (int ni = 0; ni < 8; ni++)
#pragma unroll
            for (int e = 0; e < 4; e++) sacc[ni][e] = 0.f;

#pragma unroll
        for (int k16 = 0; k16 < 4; k16++) {
            uint32_t a0, a1, a2, a3;
            {
                int row = wid * 16 + (lid & 15);
                uint32_t off = row * 128 + k16 * 32 + (lid >> 4) * 16;
                uint32_t sw = off ^ ((off >> 3) & 0x70);
                LDSM_X4(a0, a1, a2, a3, sQ + sw);
            }
#pragma unroll
            for (int nj = 0; nj < 4; nj++) {
                int row = nj * 16 + ((lid >> 4) & 1) * 8 + (lid & 7);
                uint32_t off = row * 128 + k16 * 32 + ((lid >> 3) & 1) * 16;
                uint32_t sw = off ^ ((off >> 3) & 0x70);
                uint32_t r0, r1, r2, r3;
                LDSM_X4(r0, r1, r2, r3, sK + sw);
                MMA_F16(sacc[nj * 2], a0, a1, a2, a3, r0, r1);
                MMA_F16(sacc[nj * 2 + 1], a0, a1, a2, a3, r2, r3);
            }
        }

        // ---- scale + mask + online softmax (registers) ----
        float pv[8][4];
        float vmax0 = -1e30f, vmax1 = -1e30f;
#pragma unroll
        for (int ni = 0; ni < 8; ni++) {
            int gj0 = k0 + ni * 8 + cbx;
#pragma unroll
            for (int e = 0; e < 4; e++) {
                int gj = gj0 + (e & 1);
                int gi = (e < 2) ? gi0 : gi1;
                float v = sacc[ni][e] * sc;
                v = (gj >= N_) ? -1e30f : ((gi == gj) ? NEG_MASK : v);
                pv[ni][e] = v;
                if (e < 2) vmax0 = fmaxf(vmax0, v);
                else       vmax1 = fmaxf(vmax1, v);
            }
        }
        vmax0 = fmaxf(vmax0, __shfl_xor_sync(0xffffffffu, vmax0, 1));
        vmax0 = fmaxf(vmax0, __shfl_xor_sync(0xffffffffu, vmax0, 2));
        vmax1 = fmaxf(vmax1, __shfl_xor_sync(0xffffffffu, vmax1, 1));
        vmax1 = fmaxf(vmax1, __shfl_xor_sync(0xffffffffu, vmax1, 2));

        float mn0 = fmaxf(m0r, vmax0), mn1 = fmaxf(m1r, vmax1);
        float cr0 = __expf(m0r - mn0), cr1 = __expf(m1r - mn1);
        m0r = mn0; m1r = mn1;

        float s0 = 0.f, s1 = 0.f;
        uint32_t pf[4][4];
#pragma unroll
        for (int ni = 0; ni < 8; ni++) {
            float p0 = __expf(pv[ni][0] - mn0);
            float p1 = __expf(pv[ni][1] - mn0);
            float p2 = __expf(pv[ni][2] - mn1);
            float p3 = __expf(pv[ni][3] - mn1);
            s0 += p0 + p1;
            s1 += p2 + p3;
            pf[ni >> 1][(ni & 1) * 2 + 0] = pack_h2(p0, p1);
            pf[ni >> 1][(ni & 1) * 2 + 1] = pack_h2(p2, p3);
        }
        s0 += __shfl_xor_sync(0xffffffffu, s0, 1);
        s0 += __shfl_xor_sync(0xffffffffu, s0, 2);
        s1 += __shfl_xor_sync(0xffffffffu, s1, 1);
        s1 += __shfl_xor_sync(0xffffffffu, s1, 2);
        l0r = l0r * cr0 + s0;
        l1r = l1r * cr1 + s1;
#pragma unroll
        for (int nd = 0; nd < 8; nd++) {
            oacc[nd][0] *= cr0; oacc[nd][1] *= cr0;
            oacc[nd][2] *= cr1; oacc[nd][3] *= cr1;
        }

        // ---- O += P V (P in registers; V via ldmatrix.trans) ----
#pragma unroll
        for (int ki = 0; ki < 4; ki++) {
#pragma unroll
            for (int di = 0; di < 4; di++) {
                int row = ki * 16 + (lid & 15);
                uint32_t off = row * 128 + di * 32 + (lid >> 4) * 16;
                uint32_t sw = off ^ ((off >> 3) & 0x70);
                uint32_t v0, v1, v2, v3;
                LDSM_X4_T(v0, v1, v2, v3, sV + sw);
                MMA_F16(oacc[di * 2],     pf[ki][0], pf[ki][1], pf[ki][2], pf[ki][3], v0, v1);
                MMA_F16(oacc[di * 2 + 1], pf[ki][0], pf[ki][1], pf[ki][2], pf[ki][3], v2, v3);
            }
        }
    }

    // ---- normalize and write fp16 [b, n, h*64+d] ----
    float inv0 = 1.f / l0r, inv1 = 1.f / l1r;
    if (gi0 < N_) {
        __half* dst = g_atth + ((size_t)b * N_ + gi0) * INNER + h * 64 + cbx;
#pragma unroll
        for (int nd = 0; nd < 8; nd++)
            *(__half2*)(dst + nd * 8) = __floats2half2_rn(oacc[nd][0] * inv0,
                                                          oacc[nd][1] * inv0);
    }
    if (gi1 < N_) {
        __half* dst = g_atth + ((size_t)b * N_ + gi1) * INNER + h * 64 + cbx;
#pragma unroll
        for (int nd = 0; nd < 8; nd++)
            *(__half2*)(dst + nd * 8) = __floats2half2_rn(oacc[nd][2] * inv1,
                                                          oacc[nd][3] * inv1);
    }
}

// ---------------- launch --------------------------------------------------------
extern "C" void kernel_launch(void* const* d_in, const int* in_sizes, int n_in,
                              void* d_out, int out_size)
{
    const float* x      = (const float*)d_in[0];
    const float* W_qkv  = (const float*)d_in[1];
    const float* scale  = (const float*)d_in[2];
    const float* W_out  = (const float*)d_in[3];
    const float* b_out  = (const float*)d_in[4];
    float* out = (float*)d_out;
    (void)in_sizes; (void)n_in; (void)out_size;

    const int HGEMM_SMEM = 3 * 32768;          // 98304
    const int ATTN_SMEM  = 16384 + 3 * 16384;  // 65536
    cudaFuncSetAttribute(hgemm_mma, cudaFuncAttributeMaxDynamicSharedMemorySize,
                         HGEMM_SMEM);
    cudaFuncSetAttribute(attn_mma, cudaFuncAttributeMaxDynamicSharedMemorySize,
                         ATTN_SMEM);

    __half* xh;     cudaGetSymbolAddress((void**)&xh, g_xh);
    __half* atth;   cudaGetSymbolAddress((void**)&atth, g_atth);
    __half* wqkvt;  cudaGetSymbolAddress((void**)&wqkvt, g_wqkvt);
    __half* woutt;  cudaGetSymbolAddress((void**)&woutt, g_woutt);

    int n4 = M_TOT * DIM_ / 4;
    f32_to_f16_vec<<<(n4 + 255) / 256, 256>>>(x, xh, n4);
    transpose_f16<<<dim3(2304 / 32, 768 / 32), dim3(32, 32)>>>(W_qkv, wqkvt, 768, 2304);
    transpose_f16<<<dim3(768 / 32, 768 / 32), dim3(32, 32)>>>(W_out, woutt, 768, 768);

    hgemm_mma<<<dim3(2304 / 128, (M_TOT + 127) / 128), 256, HGEMM_SMEM>>>(
        xh, wqkvt, M_TOT, 0, nullptr, nullptr);

    attn_mma<<<dim3((N_ + 127) / 128, H_, B_), 256, ATTN_SMEM>>>(scale);

    hgemm_mma<<<dim3(768 / 128, (M_TOT + 127) / 128), 256, HGEMM_SMEM>>>(
        atth, woutt, M_TOT, 1, b_out, out);
}

// round 6
// speedup vs baseline: 1.0685x; 1.0685x over previous
#include <cuda_runtime.h>
#include <cuda_fp16.h>
#include <cstdint>

#define B_    32
#define N_    577
#define H_    12
#define DH_   64
#define DIM_  768
#define INNER 768
#define M_TOT (B_ * N_)   // 18464
#define NEG_MASK (-987654321.0f)

// ---------------- scratch (device globals: no runtime allocation) -------------
__device__ __align__(128) __half g_qh[(size_t)B_ * H_ * N_ * DH_];
__device__ __align__(128) __half g_kh[(size_t)B_ * H_ * N_ * DH_];
__device__ __align__(128) __half g_vh[(size_t)B_ * H_ * N_ * DH_];
__device__ __align__(128) __half g_xh[(size_t)M_TOT * DIM_];
__device__ __align__(128) __half g_atth[(size_t)M_TOT * INNER];
__device__ __align__(128) __half g_wqkvt[(size_t)2304 * DIM_];
__device__ __align__(128) __half g_woutt[(size_t)DIM_ * INNER];

__device__ __forceinline__ uint32_t smem_to_u32(const void* p) {
    uint32_t a;
    asm("{ .reg .u64 t; cvta.to.shared.u64 t, %1; cvt.u32.u64 %0, t; }" : "=r"(a) : "l"(p));
    return a;
}

#define MMA_F16(acc, a0, a1, a2, a3, b0, b1) \
    asm volatile("mma.sync.aligned.m16n8k16.row.col.f32.f16.f16.f32 " \
        "{%0,%1,%2,%3}, {%4,%5,%6,%7}, {%8,%9}, {%0,%1,%2,%3};" \
        : "+f"((acc)[0]), "+f"((acc)[1]), "+f"((acc)[2]), "+f"((acc)[3]) \
        : "r"(a0), "r"(a1), "r"(a2), "r"(a3), "r"(b0), "r"(b1))

#define LDSM_X4(r0, r1, r2, r3, addr) \
    asm volatile("ldmatrix.sync.aligned.m8n8.x4.shared.b16 {%0,%1,%2,%3}, [%4];" \
        : "=r"(r0), "=r"(r1), "=r"(r2), "=r"(r3) : "r"(addr))

#define LDSM_X4_T(r0, r1, r2, r3, addr) \
    asm volatile("ldmatrix.sync.aligned.m8n8.x4.trans.shared.b16 {%0,%1,%2,%3}, [%4];" \
        : "=r"(r0), "=r"(r1), "=r"(r2), "=r"(r3) : "r"(addr))

__device__ __forceinline__ uint32_t pack_h2(float lo, float hi) {
    __half2 h = __floats2half2_rn(lo, hi);
    return *(uint32_t*)&h;
}

// ---------------- HMMA GEMM: 128x128 CTA tile, 4 warps, warp tile 64x64 --------
// BK=64, 2-stage cp.async double buffer.
// A [M,768] fp16 row-major; Bt [Ncols,768] fp16 (K-contiguous).
// mode 0: scatter fp16 into g_qh/g_kh/g_vh [b,h,n,d];  mode 1: +bias -> Cout fp32.
__global__ __launch_bounds__(128, 2) void hgemm_mma(
    const __half* __restrict__ A, const __half* __restrict__ Bt,
    int Mrows, int mode, const float* __restrict__ bias, float* __restrict__ Cout)
{
    extern __shared__ char smem[];
    const uint32_t sbase = smem_to_u32(smem);   // 2 bufs x (A 16K + B 16K)

    const int tid = threadIdx.x;
    const int wid = tid >> 5, lid = tid & 31;
    const int n0 = blockIdx.x * 128, m0 = blockIdx.y * 128;
    const int wm = wid >> 1, wn = wid & 1;   // warp grid 2x2, each 64x64

    float acc[4][8][4];
#pragma unroll
    for (int mi = 0; mi < 4; mi++)
#pragma unroll
        for (int ni = 0; ni < 8; ni++)
#pragma unroll
            for (int e = 0; e < 4; e++) acc[mi][ni][e] = 0.f;

    auto prefetch = [&](int c, int buf) {
        uint32_t sA = sbase + buf * 32768;
        uint32_t sB = sA + 16384;
#pragma unroll
        for (int i = 0; i < 8; i++) {
            int idx = tid + i * 128;
            int row = idx >> 3, cc = idx & 7;
            uint32_t off = row * 128 + cc * 16;
            uint32_t sw = off ^ ((off >> 3) & 0x70);
            const void* gA = A + (size_t)(m0 + row) * 768 + c * 64 + cc * 8;
            int szA = (m0 + row < Mrows) ? 16 : 0;
            asm volatile("cp.async.cg.shared.global [%0], [%1], 16, %2;"
                         :: "r"(sA + sw), "l"(gA), "r"(szA));
            const void* gB = Bt + (size_t)(n0 + row) * 768 + c * 64 + cc * 8;
            asm volatile("cp.async.cg.shared.global [%0], [%1], 16;"
                         :: "r"(sB + sw), "l"(gB));
        }
        asm volatile("cp.async.commit_group;");
    };

    prefetch(0, 0);

    for (int c = 0; c < 12; c++) {
        __syncthreads();
        if (c < 11) {
            prefetch(c + 1, (c + 1) & 1);
            asm volatile("cp.async.wait_group 1;");
        } else {
            asm volatile("cp.async.wait_group 0;");
        }
        __syncthreads();

        const uint32_t sA = sbase + (c & 1) * 32768 + (wm * 64) * 128;
        const uint32_t sB = sbase + (c & 1) * 32768 + 16384 + (wn * 64) * 128;

#pragma unroll
        for (int k16 = 0; k16 < 4; k16++) {
            uint32_t a[4][4];
#pragma unroll
            for (int mi = 0; mi < 4; mi++) {
                int row = mi * 16 + (lid & 15);
                uint32_t off = row * 128 + k16 * 32 + (lid >> 4) * 16;
                uint32_t sw = off ^ ((off >> 3) & 0x70);
                LDSM_X4(a[mi][0], a[mi][1], a[mi][2], a[mi][3], sA + sw);
            }
            uint32_t b[8][2];
#pragma unroll
            for (int nj = 0; nj < 4; nj++) {
                int row = nj * 16 + ((lid >> 4) & 1) * 8 + (lid & 7);
                uint32_t off = row * 128 + k16 * 32 + ((lid >> 3) & 1) * 16;
                uint32_t sw = off ^ ((off >> 3) & 0x70);
                uint32_t r0, r1, r2, r3;
                LDSM_X4(r0, r1, r2, r3, sB + sw);
                b[nj * 2][0] = r0;     b[nj * 2][1] = r1;
                b[nj * 2 + 1][0] = r2; b[nj * 2 + 1][1] = r3;
            }
#pragma unroll
            for (int mi = 0; mi < 4; mi++)
#pragma unroll
                for (int ni = 0; ni < 8; ni++)
                    MMA_F16(acc[mi][ni], a[mi][0], a[mi][1], a[mi][2], a[mi][3],
                            b[ni][0], b[ni][1]);
        }
    }

    const int gid = lid >> 2, qid = lid & 3;
#pragma unroll
    for (int mi = 0; mi < 4; mi++) {
#pragma unroll
        for (int half = 0; half < 2; half++) {
            int m = m0 + wm * 64 + mi * 16 + gid + half * 8;
            if (m >= Mrows) continue;
            if (mode == 0) {
                int bb = m / N_, nn = m - bb * N_;
#pragma unroll
                for (int ni = 0; ni < 8; ni++) {
                    int col = n0 + wn * 64 + ni * 8 + qid * 2;
                    int which = col / INNER;
                    int inr = col - which * INNER;
                    int hh = inr >> 6, dd = inr & 63;
                    __half* dst = ((which == 0) ? g_qh : (which == 1) ? g_kh : g_vh)
                                + ((((size_t)bb * H_ + hh) * N_ + nn) << 6) + dd;
                    *(__half2*)dst = __floats2half2_rn(acc[mi][ni][half * 2],
                                                       acc[mi][ni][half * 2 + 1]);
                }
            } else {
                float* crow = Cout + (size_t)m * 768;
#pragma unroll
                for (int ni = 0; ni < 8; ni++) {
                    int col = n0 + wn * 64 + ni * 8 + qid * 2;
                    float2 bv = *(const float2*)(bias + col);
                    *(float2*)(crow + col) = make_float2(acc[mi][ni][half * 2] + bv.x,
                                                         acc[mi][ni][half * 2 + 1] + bv.y);
                }
            }
        }
    }
}

// ---------------- prologue conversions -----------------------------------------
__global__ void f32_to_f16_vec(const float* __restrict__ in, __half* __restrict__ out, int n4)
{
    int i = blockIdx.x * blockDim.x + threadIdx.x;
    if (i < n4) {
        float4 v = ((const float4*)in)[i];
        ((__half2*)out)[2 * i + 0] = __floats2half2_rn(v.x, v.y);
        ((__half2*)out)[2 * i + 1] = __floats2half2_rn(v.z, v.w);
    }
}
__global__ void transpose_f16(const float* __restrict__ W, __half* __restrict__ Wt,
                              int rows, int cols)
{
    __shared__ float t[32][33];
    int x = blockIdx.x * 32 + threadIdx.x;
    int y = blockIdx.y * 32 + threadIdx.y;
    t[threadIdx.y][threadIdx.x] = W[(size_t)y * cols + x];
    __syncthreads();
    int xo = blockIdx.y * 32 + threadIdx.x;
    int yo = blockIdx.x * 32 + threadIdx.y;
    Wt[(size_t)yo * rows + xo] = __float2half(t[threadIdx.x][threadIdx.y]);
}

// ---------------- HMMA flash attention (R4 layout: 64 q-rows, 4 warps) ---------
// smem: Q 8KB | {K,V} x 2 bufs (16KB each) = 40960 B
__global__ __launch_bounds__(128) void attn_mma(const float* __restrict__ scale)
{
    extern __shared__ char smem[];
    const uint32_t sb = smem_to_u32(smem);
    const uint32_t sQ = sb;

    const int tid = threadIdx.x, wid = tid >> 5, lid = tid & 31;
    const int qt = blockIdx.x, h = blockIdx.y, b = blockIdx.z;
    const int q0 = qt * 64;
    const float sc = scale[h];
    const size_t hbase = (size_t)(b * H_ + h) * N_ * 64;
    const __half* Qg = g_qh + hbase;
    const __half* Kg = g_kh + hbase;
    const __half* Vg = g_vh + hbase;

#pragma unroll
    for (int i = 0; i < 4; i++) {
        int idx = tid + i * 128;
        int row = idx >> 3, cc = idx & 7;
        uint32_t off = row * 128 + cc * 16;
        uint32_t sw = off ^ ((off >> 3) & 0x70);
        const void* src = Qg + (size_t)(q0 + row) * 64 + cc * 8;
        int sz = (q0 + row < N_) ? 16 : 0;
        asm volatile("cp.async.cg.shared.global [%0], [%1], 16, %2;"
                     :: "r"(sQ + sw), "l"(src), "r"(sz));
    }
    asm volatile("cp.async.commit_group;");

    auto ldKV = [&](int kt) {
        uint32_t sK = sb + 8192 + (kt & 1) * 16384;
        uint32_t sV = sK + 8192;
        int k0 = kt * 64;
#pragma unroll
        for (int i = 0; i < 4; i++) {
            int idx = tid + i * 128;
            int row = idx >> 3, cc = idx & 7;
            uint32_t off = row * 128 + cc * 16;
            uint32_t sw = off ^ ((off >> 3) & 0x70);
            int gj = k0 + row;
            int sz = (gj < N_) ? 16 : 0;
            const void* srcK = Kg + (size_t)gj * 64 + cc * 8;
            const void* srcV = Vg + (size_t)gj * 64 + cc * 8;
            asm volatile("cp.async.cg.shared.global [%0], [%1], 16, %2;"
                         :: "r"(sK + sw), "l"(srcK), "r"(sz));
            asm volatile("cp.async.cg.shared.global [%0], [%1], 16, %2;"
                         :: "r"(sV + sw), "l"(srcV), "r"(sz));
        }
        asm volatile("cp.async.commit_group;");
    };
    ldKV(0);

    float m0r = -1e30f, m1r = -1e30f, l0r = 0.f, l1r = 0.f;
    float oacc[8][4];
#pragma unroll
    for (int nd = 0; nd < 8; nd++)
#pragma unroll
        for (int e = 0; e < 4; e++) oacc[nd][e] = 0.f;

    const int gi0 = q0 + wid * 16 + (lid >> 2);
    const int gi1 = gi0 + 8;
    const int cbx = (lid & 3) * 2;

    for (int kt = 0; kt < 10; kt++) {
        __syncthreads();
        if (kt < 9) {
            ldKV(kt + 1);
            asm volatile("cp.async.wait_group 1;");
        } else {
            asm volatile("cp.async.wait_group 0;");
        }
        __syncthreads();

        const uint32_t sK = sb + 8192 + (kt & 1) * 16384;
        const uint32_t sV = sK + 8192;
        const int k0 = kt * 64;

        float sacc[8][4];
#pragma unroll
        for (int ni = 0; ni < 8; ni++)
#pragma unroll
            for (int e = 0; e < 4; e++) sacc[ni][e] = 0.f;

#pragma unroll
        for (int k16 = 0; k16 < 4; k16++) {
            uint32_t a0, a1, a2, a3;
            {
                int row = wid * 16 + (lid & 15);
                uint32_t off = row * 128 + k16 * 32 + (lid >> 4) * 16;
                uint32_t sw = off ^ ((off >> 3) & 0x70);
                LDSM_X4(a0, a1, a2, a3, sQ + sw);
            }
#pragma unroll
            for (int nj = 0; nj < 4; nj++) {
                int row = nj * 16 + ((lid >> 4) & 1) * 8 + (lid & 7);
                uint32_t off = row * 128 + k16 * 32 + ((lid >> 3) & 1) * 16;
                uint32_t sw = off ^ ((off >> 3) & 0x70);
                uint32_t r0, r1, r2, r3;
                LDSM_X4(r0, r1, r2, r3, sK + sw);
                MMA_F16(sacc[nj * 2], a0, a1, a2, a3, r0, r1);
                MMA_F16(sacc[nj * 2 + 1], a0, a1, a2, a3, r2, r3);
            }
        }

        float pv[8][4];
        float vmax0 = -1e30f, vmax1 = -1e30f;
#pragma unroll
        for (int ni = 0; ni < 8; ni++) {
            int gj0 = k0 + ni * 8 + cbx;
#pragma unroll
            for (int e = 0; e < 4; e++) {
                int gj = gj0 + (e & 1);
                int gi = (e < 2) ? gi0 : gi1;
                float v = sacc[ni][e] * sc;
                v = (gj >= N_) ? -1e30f : ((gi == gj) ? NEG_MASK : v);
                pv[ni][e] = v;
                if (e < 2) vmax0 = fmaxf(vmax0, v);
                else       vmax1 = fmaxf(vmax1, v);
            }
        }
        vmax0 = fmaxf(vmax0, __shfl_xor_sync(0xffffffffu, vmax0, 1));
        vmax0 = fmaxf(vmax0, __shfl_xor_sync(0xffffffffu, vmax0, 2));
        vmax1 = fmaxf(vmax1, __shfl_xor_sync(0xffffffffu, vmax1, 1));
        vmax1 = fmaxf(vmax1, __shfl_xor_sync(0xffffffffu, vmax1, 2));

        float mn0 = fmaxf(m0r, vmax0), mn1 = fmaxf(m1r, vmax1);
        float cr0 = __expf(m0r - mn0), cr1 = __expf(m1r - mn1);
        m0r = mn0; m1r = mn1;

        float s0 = 0.f, s1 = 0.f;
        uint32_t pf[4][4];
#pragma unroll
        for (int ni = 0; ni < 8; ni++) {
            float p0 = __expf(pv[ni][0] - mn0);
            float p1 = __expf(pv[ni][1] - mn0);
            float p2 = __expf(pv[ni][2] - mn1);
            float p3 = __expf(pv[ni][3] - mn1);
            s0 += p0 + p1;
            s1 += p2 + p3;
            pf[ni >> 1][(ni & 1) * 2 + 0] = pack_h2(p0, p1);
            pf[ni >> 1][(ni & 1) * 2 + 1] = pack_h2(p2, p3);
        }
        s0 += __shfl_xor_sync(0xffffffffu, s0, 1);
        s0 += __shfl_xor_sync(0xffffffffu, s0, 2);
        s1 += __shfl_xor_sync(0xffffffffu, s1, 1);
        s1 += __shfl_xor_sync(0xffffffffu, s1, 2);
        l0r = l0r * cr0 + s0;
        l1r = l1r * cr1 + s1;
#pragma unroll
        for (int nd = 0; nd < 8; nd++) {
            oacc[nd][0] *= cr0; oacc[nd][1] *= cr0;
            oacc[nd][2] *= cr1; oacc[nd][3] *= cr1;
        }

#pragma unroll
        for (int ki = 0; ki < 4; ki++) {
#pragma unroll
            for (int di = 0; di < 4; di++) {
                int row = ki * 16 + (lid & 15);
                uint32_t off = row * 128 + di * 32 + (lid >> 4) * 16;
                uint32_t sw = off ^ ((off >> 3) & 0x70);
                uint32_t v0, v1, v2, v3;
                LDSM_X4_T(v0, v1, v2, v3, sV + sw);
                MMA_F16(oacc[di * 2],     pf[ki][0], pf[ki][1], pf[ki][2], pf[ki][3], v0, v1);
                MMA_F16(oacc[di * 2 + 1], pf[ki][0], pf[ki][1], pf[ki][2], pf[ki][3], v2, v3);
            }
        }
    }

    float inv0 = 1.f / l0r, inv1 = 1.f / l1r;
    if (gi0 < N_) {
        __half* dst = g_atth + ((size_t)b * N_ + gi0) * INNER + h * 64 + cbx;
#pragma unroll
        for (int nd = 0; nd < 8; nd++)
            *(__half2*)(dst + nd * 8) = __floats2half2_rn(oacc[nd][0] * inv0,
                                                          oacc[nd][1] * inv0);
    }
    if (gi1 < N_) {
        __half* dst = g_atth + ((size_t)b * N_ + gi1) * INNER + h * 64 + cbx;
#pragma unroll
        for (int nd = 0; nd < 8; nd++)
            *(__half2*)(dst + nd * 8) = __floats2half2_rn(oacc[nd][2] * inv1,
                                                          oacc[nd][3] * inv1);
    }
}

// ---------------- launch --------------------------------------------------------
extern "C" void kernel_launch(void* const* d_in, const int* in_sizes, int n_in,
                              void* d_out, int out_size)
{
    const float* x      = (const float*)d_in[0];
    const float* W_qkv  = (const float*)d_in[1];
    const float* scale  = (const float*)d_in[2];
    const float* W_out  = (const float*)d_in[3];
    const float* b_out  = (const float*)d_in[4];
    float* out = (float*)d_out;
    (void)in_sizes; (void)n_in; (void)out_size;

    const int HGEMM_SMEM = 2 * 32768;          // 65536
    const int ATTN_SMEM  = 8192 + 2 * 16384;   // 40960
    cudaFuncSetAttribute(hgemm_mma, cudaFuncAttributeMaxDynamicSharedMemorySize,
                         HGEMM_SMEM);
    cudaFuncSetAttribute(attn_mma, cudaFuncAttributeMaxDynamicSharedMemorySize,
                         ATTN_SMEM);

    __half* xh;     cudaGetSymbolAddress((void**)&xh, g_xh);
    __half* atth;   cudaGetSymbolAddress((void**)&atth, g_atth);
    __half* wqkvt;  cudaGetSymbolAddress((void**)&wqkvt, g_wqkvt);
    __half* woutt;  cudaGetSymbolAddress((void**)&woutt, g_woutt);

    int n4 = M_TOT * DIM_ / 4;
    f32_to_f16_vec<<<(n4 + 255) / 256, 256>>>(x, xh, n4);
    transpose_f16<<<dim3(2304 / 32, 768 / 32), dim3(32, 32)>>>(W_qkv, wqkvt, 768, 2304);
    transpose_f16<<<dim3(768 / 32, 768 / 32), dim3(32, 32)>>>(W_out, woutt, 768, 768);

    hgemm_mma<<<dim3(2304 / 128, (M_TOT + 127) / 128), 128, HGEMM_SMEM>>>(
        xh, wqkvt, M_TOT, 0, nullptr, nullptr);

    attn_mma<<<dim3((N_ + 63) / 64, H_, B_), 128, ATTN_SMEM>>>(scale);

    hgemm_mma<<<dim3(768 / 128, (M_TOT + 127) / 128), 128, HGEMM_SMEM>>>(
        atth, woutt, M_TOT, 1, b_out, out);
}